// round 1
// baseline (speedup 1.0000x reference)
#include <cuda_runtime.h>
#include <math.h>

#define ENC 2048
#define DEC 512
#define ATTD 512
#define BATCH 256
#define LSEQ 196
#define MROWS (BATCH * LSEQ)   // 50176, divisible by 64

// Scratch (device globals: no allocation allowed in kernel_launch)
__device__ float g_att2[BATCH * ATTD];  // h@W_dec + b_dec + b_enc  [B, ATT]
__device__ float g_gate[BATCH];         // sigmoid(h@W_beta + b_beta)
__device__ float g_att[MROWS];          // pre-softmax attention logits (b_full dropped: softmax-invariant)

// ---------------------------------------------------------------------------
// Kernel 1: att2[b,a] = h[b,:] @ W_dec[:,a] + b_dec[a] + b_enc[a]; gate[b]
// grid 256 blocks (one per b), 256 threads
// ---------------------------------------------------------------------------
__global__ __launch_bounds__(256) void att2_kernel(
    const float* __restrict__ h, const float* __restrict__ W_dec,
    const float* __restrict__ b_dec, const float* __restrict__ b_enc,
    const float* __restrict__ W_beta, const float* __restrict__ b_beta) {
    int b = blockIdx.x;
    int t = threadIdx.x;
    __shared__ float hs[DEC];
    __shared__ float red[256];

    hs[t]       = h[b * DEC + t];
    hs[t + 256] = h[b * DEC + t + 256];
    __syncthreads();

    float acc0 = 0.f, acc1 = 0.f;
#pragma unroll 8
    for (int k = 0; k < DEC; k++) {
        float hv = hs[k];
        acc0 += hv * W_dec[k * ATTD + t];
        acc1 += hv * W_dec[k * ATTD + t + 256];
    }
    g_att2[b * ATTD + t]       = acc0 + b_dec[t]       + b_enc[t];
    g_att2[b * ATTD + t + 256] = acc1 + b_dec[t + 256] + b_enc[t + 256];

    // gate_beta
    float p = hs[t] * W_beta[t] + hs[t + 256] * W_beta[t + 256];
    red[t] = p;
    __syncthreads();
    for (int s = 128; s > 0; s >>= 1) {
        if (t < s) red[t] += red[t + s];
        __syncthreads();
    }
    if (t == 0) g_gate[b] = 1.f / (1.f + expf(-(red[0] + b_beta[0])));
}

// ---------------------------------------------------------------------------
// Kernel 2: main GEMM + fused relu-reduce.
//   For each flattened row m in [0, 50176): att[m] = sum_a relu( x[m,:]@W_enc[:,a] + att2[b(m),a] ) * W_full[a]
// Tiling: BM=64 rows x BN=64 cols x BK=16, 128 threads, 8x4 microtile.
// 8 n-chunks sequential per block, relu-reduced into att_acc.
// ---------------------------------------------------------------------------
#define BM 64
#define BN 64
#define BK 16
#define TM 8
#define TN 4

__global__ __launch_bounds__(128) void att_gemm_kernel(
    const float* __restrict__ x, const float* __restrict__ W_enc,
    const float* __restrict__ W_full) {
    __shared__ float xs[BK][BM + 4];
    __shared__ float ws[BK][BN];
    __shared__ float wf[ATTD];
    __shared__ float att_acc[BM];
    __shared__ float red[BM][17];

    const int t = threadIdx.x;
    const int ty = t >> 4;      // 0..7  (row groups)
    const int tx = t & 15;      // 0..15 (col groups)
    const int row0 = blockIdx.x * BM;

    if (t < BM) att_acc[t] = 0.f;
    for (int i = t; i < ATTD; i += 128) wf[i] = W_full[i];
    __syncthreads();

    for (int nc = 0; nc < ATTD / BN; nc++) {
        const int a0 = nc * BN;
        float acc[TM][TN];
#pragma unroll
        for (int i = 0; i < TM; i++)
#pragma unroll
            for (int j = 0; j < TN; j++) acc[i][j] = 0.f;

        for (int k0 = 0; k0 < ENC; k0 += BK) {
            // x tile: 64 rows x 16 k = 256 float4, 2 per thread (transposed store)
#pragma unroll
            for (int i = 0; i < 2; i++) {
                int idx = t * 2 + i;            // 0..255
                int r = idx >> 2;               // 0..63
                int kp = (idx & 3) * 4;         // 0,4,8,12
                float4 v = *reinterpret_cast<const float4*>(
                    &x[(size_t)(row0 + r) * ENC + k0 + kp]);
                xs[kp + 0][r] = v.x;
                xs[kp + 1][r] = v.y;
                xs[kp + 2][r] = v.z;
                xs[kp + 3][r] = v.w;
            }
            // W_enc tile: 16 k x 64 a = 256 float4, 2 per thread
#pragma unroll
            for (int i = 0; i < 2; i++) {
                int idx = t * 2 + i;
                int kk = idx >> 4;              // 0..15
                int ap = (idx & 15) * 4;        // 0..60
                *reinterpret_cast<float4*>(&ws[kk][ap]) =
                    *reinterpret_cast<const float4*>(
                        &W_enc[(size_t)(k0 + kk) * ATTD + a0 + ap]);
            }
            __syncthreads();

#pragma unroll
            for (int k = 0; k < BK; k++) {
                float xf[TM], wfr[TN];
#pragma unroll
                for (int i = 0; i < TM; i++) xf[i] = xs[k][ty * TM + i];
#pragma unroll
                for (int j = 0; j < TN; j++) wfr[j] = ws[k][tx * TN + j];
#pragma unroll
                for (int i = 0; i < TM; i++)
#pragma unroll
                    for (int j = 0; j < TN; j++) acc[i][j] += xf[i] * wfr[j];
            }
            __syncthreads();
        }

        // Epilogue for this n-chunk: + att2, relu, dot W_full, partial row sums
#pragma unroll
        for (int i = 0; i < TM; i++) {
            int r = row0 + ty * TM + i;
            int b = r / LSEQ;
            const float* a2 = &g_att2[b * ATTD + a0 + tx * TN];
            float p = 0.f;
#pragma unroll
            for (int j = 0; j < TN; j++) {
                float v = acc[i][j] + a2[j];
                v = fmaxf(v, 0.f);
                p += v * wf[a0 + tx * TN + j];
            }
            red[ty * TM + i][tx] = p;
        }
        __syncthreads();
        if (t < BM) {
            float s = 0.f;
#pragma unroll
            for (int j = 0; j < 16; j++) s += red[t][j];
            att_acc[t] += s;
        }
        __syncthreads();
    }
    if (t < BM) g_att[row0 + t] = att_acc[t];
}

// ---------------------------------------------------------------------------
// Kernel 3a: alpha = softmax(att, axis=L). One block per b.
// ---------------------------------------------------------------------------
__global__ __launch_bounds__(256) void softmax_kernel(float* __restrict__ out_alpha) {
    int b = blockIdx.x;
    int t = threadIdx.x;
    __shared__ float sred[256];

    float v = (t < LSEQ) ? g_att[b * LSEQ + t] : -1e30f;
    sred[t] = v;
    __syncthreads();
    for (int s = 128; s > 0; s >>= 1) {
        if (t < s) sred[t] = fmaxf(sred[t], sred[t + s]);
        __syncthreads();
    }
    float m = sred[0];
    __syncthreads();
    float e = (t < LSEQ) ? expf(v - m) : 0.f;
    sred[t] = e;
    __syncthreads();
    for (int s = 128; s > 0; s >>= 1) {
        if (t < s) sred[t] += sred[t + s];
        __syncthreads();
    }
    float inv = 1.f / sred[0];
    if (t < LSEQ) out_alpha[b * LSEQ + t] = e * inv;
}

// ---------------------------------------------------------------------------
// Kernel 3b: z[b,c] = gate[b] * sum_l alpha[b,l] * x[b,l,c]
// grid (ENC/256=8, B=256), 256 threads, thread owns one c column.
// ---------------------------------------------------------------------------
__global__ __launch_bounds__(256) void z_kernel(
    const float* __restrict__ x, const float* __restrict__ alpha,
    float* __restrict__ out_z) {
    int b = blockIdx.y;
    int c = blockIdx.x * 256 + threadIdx.x;
    __shared__ float sal[LSEQ];
    for (int i = threadIdx.x; i < LSEQ; i += 256) sal[i] = alpha[b * LSEQ + i];
    __syncthreads();

    const float* xp = x + (size_t)b * LSEQ * ENC + c;
    float acc = 0.f;
#pragma unroll 4
    for (int l = 0; l < LSEQ; l++) acc += sal[l] * xp[(size_t)l * ENC];
    out_z[b * ENC + c] = g_gate[b] * acc;
}

// ---------------------------------------------------------------------------
// Launch. Inputs in metadata order:
// 0:x 1:h 2:W_enc 3:b_enc 4:W_dec 5:b_dec 6:W_full 7:b_full 8:W_beta 9:b_beta
// Output: [ gate*z (B*ENC) | alpha (B*L) ]
// ---------------------------------------------------------------------------
extern "C" void kernel_launch(void* const* d_in, const int* in_sizes, int n_in,
                              void* d_out, int out_size) {
    const float* x      = (const float*)d_in[0];
    const float* h      = (const float*)d_in[1];
    const float* W_enc  = (const float*)d_in[2];
    const float* b_enc  = (const float*)d_in[3];
    const float* W_dec  = (const float*)d_in[4];
    const float* b_dec  = (const float*)d_in[5];
    const float* W_full = (const float*)d_in[6];
    // d_in[7] = b_full: softmax-invariant, unused.
    const float* W_beta = (const float*)d_in[8];
    const float* b_beta = (const float*)d_in[9];

    float* out = (float*)d_out;
    float* out_z = out;                        // [B, ENC]
    float* out_alpha = out + (size_t)BATCH * ENC;  // [B, L]

    att2_kernel<<<BATCH, 256>>>(h, W_dec, b_dec, b_enc, W_beta, b_beta);
    att_gemm_kernel<<<MROWS / BM, 128>>>(x, W_enc, W_full);
    softmax_kernel<<<BATCH, 256>>>(out_alpha);
    z_kernel<<<dim3(ENC / 256, BATCH), 256>>>(x, out_alpha, out_z);
}

// round 3
// speedup vs baseline: 2.3913x; 2.3913x over previous
#include <cuda_runtime.h>
#include <cuda_bf16.h>
#include <cstdint>
#include <math.h>

#define ENC 2048
#define DEC 512
#define ATTD 512
#define BATCH 256
#define LSEQ 196
#define MROWS (BATCH * LSEQ)      // 50176
#define TILE_M 128
#define NCTA (MROWS / TILE_M)     // 392
#define KB 64                     // k elems per pipeline stage
#define NKB (ENC / KB)            // 32
#define NB_CHUNKS 4               // 512 / 128
#define STAGE_BYTES 65536         // x(hi16K+lo16K) + w(hi16K+lo16K)
#define DYN_BYTES (2 * STAGE_BYTES + 128)

// ---------------- scratch globals ----------------
__device__ float g_att2[BATCH * ATTD];
__device__ float g_gate[BATCH];
__device__ float g_att[MROWS];
// W transposed + bf16-split: [hl][n=512][k=2048] bf16
__device__ __align__(16) unsigned char g_Wt[2u * 512u * 2048u * 2u];

// ---------------- helpers ----------------
__device__ __forceinline__ uint32_t smem_u32(const void* p) {
    uint32_t a;
    asm("{ .reg .u64 t; cvta.to.shared.u64 t, %1; cvt.u32.u64 %0, t; }" : "=r"(a) : "l"(p));
    return a;
}
__device__ __forceinline__ uint32_t pack2(float a, float b) {
    __nv_bfloat162 t = __floats2bfloat162_rn(a, b);
    return *reinterpret_cast<uint32_t*>(&t);
}
#define LDSM_X4(r, addr) \
    asm volatile("ldmatrix.sync.aligned.m8n8.x4.shared.b16 {%0,%1,%2,%3}, [%4];" \
        : "=r"((r)[0]), "=r"((r)[1]), "=r"((r)[2]), "=r"((r)[3]) : "r"(addr))
#define MMA_BF16(c, a, b) \
    asm volatile("mma.sync.aligned.m16n8k16.row.col.f32.bf16.bf16.f32 " \
        "{%0,%1,%2,%3}, {%4,%5,%6,%7}, {%8,%9}, {%0,%1,%2,%3};" \
        : "+f"((c)[0]), "+f"((c)[1]), "+f"((c)[2]), "+f"((c)[3]) \
        : "r"((a)[0]), "r"((a)[1]), "r"((a)[2]), "r"((a)[3]), "r"((b)[0]), "r"((b)[1]))
#define CP_ASYNC16(dst, src) \
    asm volatile("cp.async.ca.shared.global [%0], [%1], 16;" :: "r"(dst), "l"(src) : "memory")
#define CP_COMMIT() asm volatile("cp.async.commit_group;" ::: "memory")
#define CP_WAIT0()  asm volatile("cp.async.wait_group 0;" ::: "memory")

// ---------------------------------------------------------------------------
// prep: W_enc [2048 k][512 n] fp32 -> g_Wt bf16 [hl][n][k]
// ---------------------------------------------------------------------------
__global__ __launch_bounds__(256) void prep_w(const float* __restrict__ W_enc) {
    __shared__ float tile[64][65];
    const int k0 = blockIdx.x * 64, n0 = blockIdx.y * 64;
    const int tid = threadIdx.x;
    for (int i = tid; i < 64 * 64; i += 256) {
        int kk = i >> 6, nn = i & 63;
        tile[kk][nn] = W_enc[(size_t)(k0 + kk) * ATTD + n0 + nn];
    }
    __syncthreads();
    for (int i = tid; i < 1024; i += 256) {
        int hl = i >> 9, rem = i & 511;
        int nn = rem >> 3, ch = rem & 7;
        uint32_t w[4];
#pragma unroll
        for (int j = 0; j < 4; j++) {
            float v0 = tile[ch * 8 + 2 * j][nn], v1 = tile[ch * 8 + 2 * j + 1][nn];
            float h0 = __bfloat162float(__float2bfloat16_rn(v0));
            float h1 = __bfloat162float(__float2bfloat16_rn(v1));
            w[j] = hl ? pack2(v0 - h0, v1 - h1) : pack2(h0, h1);
        }
        *reinterpret_cast<uint4*>(g_Wt + (size_t)hl * 2097152 +
                                  (size_t)(n0 + nn) * 4096 + (size_t)(k0 + ch * 8) * 2) =
            make_uint4(w[0], w[1], w[2], w[3]);
    }
}

// ---------------------------------------------------------------------------
// att2 + gate (unchanged)
// ---------------------------------------------------------------------------
__global__ __launch_bounds__(256) void att2_kernel(
    const float* __restrict__ h, const float* __restrict__ W_dec,
    const float* __restrict__ b_dec, const float* __restrict__ b_enc,
    const float* __restrict__ W_beta, const float* __restrict__ b_beta) {
    int b = blockIdx.x, t = threadIdx.x;
    __shared__ float hs[DEC];
    __shared__ float red[256];
    hs[t] = h[b * DEC + t];
    hs[t + 256] = h[b * DEC + t + 256];
    __syncthreads();
    float acc0 = 0.f, acc1 = 0.f;
#pragma unroll 8
    for (int k = 0; k < DEC; k++) {
        float hv = hs[k];
        acc0 += hv * W_dec[k * ATTD + t];
        acc1 += hv * W_dec[k * ATTD + t + 256];
    }
    g_att2[b * ATTD + t] = acc0 + b_dec[t] + b_enc[t];
    g_att2[b * ATTD + t + 256] = acc1 + b_dec[t + 256] + b_enc[t + 256];
    float p = hs[t] * W_beta[t] + hs[t + 256] * W_beta[t + 256];
    red[t] = p;
    __syncthreads();
    for (int s = 128; s > 0; s >>= 1) {
        if (t < s) red[t] += red[t + s];
        __syncthreads();
    }
    if (t == 0) g_gate[b] = 1.f / (1.f + expf(-(red[0] + b_beta[0])));
}

// ---------------------------------------------------------------------------
// Main GEMM: att[m] = sum_n relu( (x@W_enc)[m,n] + att2[b(m),n] ) * W_full[n]
// via 3-pass bf16 mma.sync. 8 warps = 4(m) x 2(n); warp tile m32 x n64.
// ---------------------------------------------------------------------------
__global__ __launch_bounds__(256, 1) void att_gemm_mma(
    const float* __restrict__ x, const float* __restrict__ W_full) {
    extern __shared__ unsigned char dynraw[];
    __shared__ float wf_s[ATTD];
    __shared__ float att_acc[TILE_M];

    const int tid = threadIdx.x;
    const int lane = tid & 31;
    const int wid = tid >> 5;
    const int wm = wid >> 1;   // 0..3
    const int wn = wid & 1;    // 0..1
    const int row0 = blockIdx.x * TILE_M;

    uint32_t rawb = smem_u32(dynraw);
    uint32_t dynb = (rawb + 127u) & ~127u;
    unsigned char* dyn = dynraw + (dynb - rawb);

    for (int i = tid; i < ATTD; i += 256) wf_s[i] = W_full[i];
    if (tid < TILE_M) att_acc[tid] = 0.f;
    __syncthreads();

    // ---- loader mappings ----
    const int xm = tid >> 1, xh = tid & 1;   // x: row xm, k-half xh (32 elems)
    const float4* xg = reinterpret_cast<const float4*>(x) +
                       ((size_t)(row0 + xm) * ENC) / 4 + xh * 8;
    const int xm7 = xm & 7;
    const int wrow = tid >> 1, wkh = tid & 1;  // W: n-row wrow, k-half wkh
    const int wrow7 = wrow & 7;

    // ldmatrix lane geometry
    const int a_r = wm * 32 + (lane & 7) + (lane & 8);      // + mt*16
    const int a_hi = lane >> 4;
    const int b_r = wn * 64 + (lane & 7) + ((lane >> 1) & 8);  // + ntp*16
    const int b_hi = (lane >> 3) & 1;

    for (int nb = 0; nb < NB_CHUNKS; nb++) {
        float acc[2][8][4];
#pragma unroll
        for (int mt = 0; mt < 2; mt++)
#pragma unroll
            for (int nt = 0; nt < 8; nt++)
#pragma unroll
                for (int q = 0; q < 4; q++) acc[mt][nt][q] = 0.f;

        float4 xr[8];
        // ---- prologue: stage 0 ----
#pragma unroll
        for (int j = 0; j < 8; j++) xr[j] = xg[j];
        {
            unsigned char* xh_p = dyn;            // stage0 x hi
            unsigned char* xl_p = dyn + 16384;    // stage0 x lo
            const float* e = reinterpret_cast<const float*>(xr);
#pragma unroll
            for (int j = 0; j < 4; j++) {
                uint32_t hw[4], lw[4];
#pragma unroll
                for (int q = 0; q < 4; q++) {
                    float v0 = e[8 * j + 2 * q], v1 = e[8 * j + 2 * q + 1];
                    float h0 = __bfloat162float(__float2bfloat16_rn(v0));
                    float h1 = __bfloat162float(__float2bfloat16_rn(v1));
                    hw[q] = pack2(h0, h1);
                    lw[q] = pack2(v0 - h0, v1 - h1);
                }
                int swo = xm * 128 + (((xh * 4 + j) ^ xm7) << 4);
                *reinterpret_cast<uint4*>(xh_p + swo) = make_uint4(hw[0], hw[1], hw[2], hw[3]);
                *reinterpret_cast<uint4*>(xl_p + swo) = make_uint4(lw[0], lw[1], lw[2], lw[3]);
            }
        }
#pragma unroll
        for (int hl = 0; hl < 2; hl++)
#pragma unroll
            for (int j = 0; j < 4; j++) {
                uint32_t dst = dynb + 32768 + hl * 16384 + wrow * 128 +
                               (((wkh * 4 + j) ^ wrow7) << 4);
                const unsigned char* src = g_Wt + (size_t)hl * 2097152 +
                    (size_t)(nb * 128 + wrow) * 4096 + (size_t)(wkh * 32 + j * 8) * 2;
                CP_ASYNC16(dst, src);
            }
        CP_COMMIT();

        for (int kblk = 0; kblk < NKB; kblk++) {
            const int s = kblk & 1;
            const bool more = (kblk + 1 < NKB);
            if (more) {
                const float4* p = xg + (kblk + 1) * 16;
#pragma unroll
                for (int j = 0; j < 8; j++) xr[j] = p[j];
            }
            CP_WAIT0();
            __syncthreads();   // stage s (x STS + W cp.async) visible

            if (more) {
                const int ns = s ^ 1;
#pragma unroll
                for (int hl = 0; hl < 2; hl++)
#pragma unroll
                    for (int j = 0; j < 4; j++) {
                        uint32_t dst = dynb + ns * STAGE_BYTES + 32768 + hl * 16384 +
                                       wrow * 128 + (((wkh * 4 + j) ^ wrow7) << 4);
                        const unsigned char* src = g_Wt + (size_t)hl * 2097152 +
                            (size_t)(nb * 128 + wrow) * 4096 +
                            (size_t)((kblk + 1) * 64 + wkh * 32 + j * 8) * 2;
                        CP_ASYNC16(dst, src);
                    }
                CP_COMMIT();
            }

            // ---- MMA on stage s ----
            {
                const uint32_t xsb = dynb + s * STAGE_BYTES;
                const uint32_t wsb = xsb + 32768;
#pragma unroll
                for (int ks = 0; ks < 4; ks++) {
                    uint32_t ah[2][4], al[2][4], bh[4][4], bl[4][4];
#pragma unroll
                    for (int mt = 0; mt < 2; mt++) {
                        int row = a_r + mt * 16;
                        uint32_t ad = xsb + row * 128 + (((ks * 2 + a_hi) ^ (row & 7)) << 4);
                        LDSM_X4(ah[mt], ad);
                        LDSM_X4(al[mt], ad + 16384);
                    }
#pragma unroll
                    for (int ntp = 0; ntp < 4; ntp++) {
                        int row = b_r + ntp * 16;
                        uint32_t bd = wsb + row * 128 + (((ks * 2 + b_hi) ^ (row & 7)) << 4);
                        LDSM_X4(bh[ntp], bd);
                        LDSM_X4(bl[ntp], bd + 16384);
                    }
#pragma unroll
                    for (int mt = 0; mt < 2; mt++)
#pragma unroll
                        for (int ntp = 0; ntp < 4; ntp++) {
                            MMA_BF16(acc[mt][2 * ntp],     ah[mt], bh[ntp] + 0);
                            MMA_BF16(acc[mt][2 * ntp + 1], ah[mt], bh[ntp] + 2);
                            MMA_BF16(acc[mt][2 * ntp],     ah[mt], bl[ntp] + 0);
                            MMA_BF16(acc[mt][2 * ntp + 1], ah[mt], bl[ntp] + 2);
                            MMA_BF16(acc[mt][2 * ntp],     al[mt], bh[ntp] + 0);
                            MMA_BF16(acc[mt][2 * ntp + 1], al[mt], bh[ntp] + 2);
                        }
                }
            }

            if (more) {
                const int ns = s ^ 1;
                unsigned char* xh_p = dyn + ns * STAGE_BYTES;
                unsigned char* xl_p = xh_p + 16384;
                const float* e = reinterpret_cast<const float*>(xr);
#pragma unroll
                for (int j = 0; j < 4; j++) {
                    uint32_t hw[4], lw[4];
#pragma unroll
                    for (int q = 0; q < 4; q++) {
                        float v0 = e[8 * j + 2 * q], v1 = e[8 * j + 2 * q + 1];
                        float h0 = __bfloat162float(__float2bfloat16_rn(v0));
                        float h1 = __bfloat162float(__float2bfloat16_rn(v1));
                        hw[q] = pack2(h0, h1);
                        lw[q] = pack2(v0 - h0, v1 - h1);
                    }
                    int swo = xm * 128 + (((xh * 4 + j) ^ xm7) << 4);
                    *reinterpret_cast<uint4*>(xh_p + swo) = make_uint4(hw[0], hw[1], hw[2], hw[3]);
                    *reinterpret_cast<uint4*>(xl_p + swo) = make_uint4(lw[0], lw[1], lw[2], lw[3]);
                }
            }
            __syncthreads();   // protect stage buffers before next-iter writes
        }

        // ---- epilogue for this n-chunk ----
#pragma unroll
        for (int mt = 0; mt < 2; mt++)
#pragma unroll
            for (int rh = 0; rh < 2; rh++) {
                int ml = wm * 32 + mt * 16 + (lane >> 2) + rh * 8;
                int gm = row0 + ml;
                int b = gm / LSEQ;
                const float* a2 = g_att2 + (size_t)b * ATTD + nb * 128 + wn * 64;
                const float* wfp = wf_s + nb * 128 + wn * 64;
                float s = 0.f;
#pragma unroll
                for (int nt = 0; nt < 8; nt++) {
#pragma unroll
                    for (int e2 = 0; e2 < 2; e2++) {
                        int nn = nt * 8 + (lane & 3) * 2 + e2;
                        float v = acc[mt][nt][rh * 2 + e2] + __ldg(a2 + nn);
                        s += fmaxf(v, 0.f) * wfp[nn];
                    }
                }
                s += __shfl_xor_sync(0xFFFFFFFF, s, 1);
                s += __shfl_xor_sync(0xFFFFFFFF, s, 2);
                if ((lane & 3) == 0) atomicAdd(&att_acc[ml], s);
            }
        __syncthreads();
    }

    if (tid < TILE_M) g_att[row0 + tid] = att_acc[tid];
}

// ---------------------------------------------------------------------------
__global__ __launch_bounds__(256) void softmax_kernel(float* __restrict__ out_alpha) {
    int b = blockIdx.x, t = threadIdx.x;
    __shared__ float sred[256];
    float v = (t < LSEQ) ? g_att[b * LSEQ + t] : -1e30f;
    sred[t] = v;
    __syncthreads();
    for (int s = 128; s > 0; s >>= 1) {
        if (t < s) sred[t] = fmaxf(sred[t], sred[t + s]);
        __syncthreads();
    }
    float m = sred[0];
    __syncthreads();
    float e = (t < LSEQ) ? expf(v - m) : 0.f;
    sred[t] = e;
    __syncthreads();
    for (int s = 128; s > 0; s >>= 1) {
        if (t < s) sred[t] += sred[t + s];
        __syncthreads();
    }
    float inv = 1.f / sred[0];
    if (t < LSEQ) out_alpha[b * LSEQ + t] = e * inv;
}

__global__ __launch_bounds__(256) void z_kernel(
    const float* __restrict__ x, const float* __restrict__ alpha,
    float* __restrict__ out_z) {
    int b = blockIdx.y;
    int c4 = blockIdx.x * 256 + threadIdx.x;
    __shared__ float sal[LSEQ];
    for (int i = threadIdx.x; i < LSEQ; i += 256) sal[i] = alpha[b * LSEQ + i];
    __syncthreads();
    const float4* xp = reinterpret_cast<const float4*>(x + (size_t)b * LSEQ * ENC) + c4;
    float ax = 0.f, ay = 0.f, az = 0.f, aw = 0.f;
#pragma unroll 4
    for (int l = 0; l < LSEQ; l++) {
        float4 v = xp[(size_t)l * (ENC / 4)];
        float a = sal[l];
        ax += a * v.x; ay += a * v.y; az += a * v.z; aw += a * v.w;
    }
    float g = g_gate[b];
    float4 o;
    o.x = g * ax; o.y = g * ay; o.z = g * az; o.w = g * aw;
    reinterpret_cast<float4*>(out_z)[(size_t)b * (ENC / 4) + c4] = o;
}

// ---------------------------------------------------------------------------
extern "C" void kernel_launch(void* const* d_in, const int* in_sizes, int n_in,
                              void* d_out, int out_size) {
    const float* x      = (const float*)d_in[0];
    const float* h      = (const float*)d_in[1];
    const float* W_enc  = (const float*)d_in[2];
    const float* b_enc  = (const float*)d_in[3];
    const float* W_dec  = (const float*)d_in[4];
    const float* b_dec  = (const float*)d_in[5];
    const float* W_full = (const float*)d_in[6];
    // d_in[7] = b_full: softmax-invariant, unused.
    const float* W_beta = (const float*)d_in[8];
    const float* b_beta = (const float*)d_in[9];

    float* out = (float*)d_out;
    float* out_z = out;
    float* out_alpha = out + (size_t)BATCH * ENC;

    cudaFuncSetAttribute(att_gemm_mma, cudaFuncAttributeMaxDynamicSharedMemorySize, DYN_BYTES);

    prep_w<<<dim3(ENC / 64, ATTD / 64), 256>>>(W_enc);
    att2_kernel<<<BATCH, 256>>>(h, W_dec, b_dec, b_enc, W_beta, b_beta);
    att_gemm_mma<<<NCTA, 256, DYN_BYTES>>>(x, W_full);
    softmax_kernel<<<BATCH, 256>>>(out_alpha);
    z_kernel<<<dim3(ENC / 1024, BATCH), 256>>>(x, out_alpha, out_z);
}

// round 4
// speedup vs baseline: 3.0192x; 1.2625x over previous
#include <cuda_runtime.h>
#include <cuda_bf16.h>
#include <cstdint>
#include <math.h>

#define ENC 2048
#define DEC 512
#define ATTD 512
#define BATCH 256
#define LSEQ 196
#define MROWS (BATCH * LSEQ)      // 50176
#define TILE_M 128
#define NCTA (MROWS / TILE_M)     // 392
#define KBLK 32                   // k elems per pipeline stage
#define NKB (ENC / KBLK)          // 64
#define NB_CHUNKS 2               // 512 / 256
#define NSTG 4
#define XSTG 16384                // x stage: 128 rows x 32k x 2B x 2(hi/lo)
#define WSTG 32768                // W stage: 256 rows x 32k x 2B x 2(hi/lo)
#define WBASE (NSTG * XSTG)       // 65536
#define DYN_BYTES (WBASE + NSTG * WSTG + 128)  // 196736

// ---------------- scratch globals ----------------
__device__ float g_att2[BATCH * ATTD];
__device__ float g_gate[BATCH];
__device__ float g_att[MROWS];
// W transposed + bf16-split: [hl][n=512][k=2048] bf16
__device__ __align__(16) unsigned char g_Wt[2u * 512u * 2048u * 2u];

// ---------------- helpers ----------------
__device__ __forceinline__ uint32_t smem_u32(const void* p) {
    uint32_t a;
    asm("{ .reg .u64 t; cvta.to.shared.u64 t, %1; cvt.u32.u64 %0, t; }" : "=r"(a) : "l"(p));
    return a;
}
__device__ __forceinline__ uint32_t pack2(float a, float b) {
    __nv_bfloat162 t = __floats2bfloat162_rn(a, b);
    return *reinterpret_cast<uint32_t*>(&t);
}
#define LDSM_X4(r, addr) \
    asm volatile("ldmatrix.sync.aligned.m8n8.x4.shared.b16 {%0,%1,%2,%3}, [%4];" \
        : "=r"((r)[0]), "=r"((r)[1]), "=r"((r)[2]), "=r"((r)[3]) : "r"(addr))
#define MMA_BF16(c, a, b) \
    asm volatile("mma.sync.aligned.m16n8k16.row.col.f32.bf16.bf16.f32 " \
        "{%0,%1,%2,%3}, {%4,%5,%6,%7}, {%8,%9}, {%0,%1,%2,%3};" \
        : "+f"((c)[0]), "+f"((c)[1]), "+f"((c)[2]), "+f"((c)[3]) \
        : "r"((a)[0]), "r"((a)[1]), "r"((a)[2]), "r"((a)[3]), "r"((b)[0]), "r"((b)[1]))
#define CP_ASYNC16(dst, src) \
    asm volatile("cp.async.ca.shared.global [%0], [%1], 16;" :: "r"(dst), "l"(src) : "memory")
#define CP_COMMIT() asm volatile("cp.async.commit_group;" ::: "memory")
#define CP_WAIT2()  asm volatile("cp.async.wait_group 2;" ::: "memory")
#define CP_WAIT0()  asm volatile("cp.async.wait_group 0;" ::: "memory")

// ---------------------------------------------------------------------------
// prep: W_enc [2048 k][512 n] fp32 -> g_Wt bf16 [hl][n][k]
// ---------------------------------------------------------------------------
__global__ __launch_bounds__(256) void prep_w(const float* __restrict__ W_enc) {
    __shared__ float tile[64][65];
    const int k0 = blockIdx.x * 64, n0 = blockIdx.y * 64;
    const int tid = threadIdx.x;
    for (int i = tid; i < 64 * 64; i += 256) {
        int kk = i >> 6, nn = i & 63;
        tile[kk][nn] = W_enc[(size_t)(k0 + kk) * ATTD + n0 + nn];
    }
    __syncthreads();
    for (int i = tid; i < 1024; i += 256) {
        int hl = i >> 9, rem = i & 511;
        int nn = rem >> 3, ch = rem & 7;
        uint32_t w[4];
#pragma unroll
        for (int j = 0; j < 4; j++) {
            float v0 = tile[ch * 8 + 2 * j][nn], v1 = tile[ch * 8 + 2 * j + 1][nn];
            float h0 = __bfloat162float(__float2bfloat16_rn(v0));
            float h1 = __bfloat162float(__float2bfloat16_rn(v1));
            w[j] = hl ? pack2(v0 - h0, v1 - h1) : pack2(h0, h1);
        }
        *reinterpret_cast<uint4*>(g_Wt + (size_t)hl * 2097152 +
                                  (size_t)(n0 + nn) * 4096 + (size_t)(k0 + ch * 8) * 2) =
            make_uint4(w[0], w[1], w[2], w[3]);
    }
}

// ---------------------------------------------------------------------------
// att2 + gate
// ---------------------------------------------------------------------------
__global__ __launch_bounds__(256) void att2_kernel(
    const float* __restrict__ h, const float* __restrict__ W_dec,
    const float* __restrict__ b_dec, const float* __restrict__ b_enc,
    const float* __restrict__ W_beta, const float* __restrict__ b_beta) {
    int b = blockIdx.x, t = threadIdx.x;
    __shared__ float hs[DEC];
    __shared__ float red[256];
    hs[t] = h[b * DEC + t];
    hs[t + 256] = h[b * DEC + t + 256];
    __syncthreads();
    float acc0 = 0.f, acc1 = 0.f;
#pragma unroll 8
    for (int k = 0; k < DEC; k++) {
        float hv = hs[k];
        acc0 += hv * W_dec[k * ATTD + t];
        acc1 += hv * W_dec[k * ATTD + t + 256];
    }
    g_att2[b * ATTD + t] = acc0 + b_dec[t] + b_enc[t];
    g_att2[b * ATTD + t + 256] = acc1 + b_dec[t + 256] + b_enc[t + 256];
    float p = hs[t] * W_beta[t] + hs[t + 256] * W_beta[t + 256];
    red[t] = p;
    __syncthreads();
    for (int s = 128; s > 0; s >>= 1) {
        if (t < s) red[t] += red[t + s];
        __syncthreads();
    }
    if (t == 0) g_gate[b] = 1.f / (1.f + expf(-(red[0] + b_beta[0])));
}

// ---------------------------------------------------------------------------
// Main GEMM: 3-pass bf16 mma.sync, 4-stage cp.async pipeline, 1 barrier/kblk.
// 8 warps = 4(m) x 2(n); warp tile m32 x n128. N chunks of 256 (2 passes).
// ---------------------------------------------------------------------------
__global__ __launch_bounds__(256, 1) void att_gemm_mma(
    const float* __restrict__ x, const float* __restrict__ W_full) {
    extern __shared__ unsigned char dynraw[];
    __shared__ float wf_s[ATTD];
    __shared__ float att_acc[TILE_M];

    const int tid = threadIdx.x;
    const int lane = tid & 31;
    const int wid = tid >> 5;
    const int wm = wid >> 1;   // 0..3
    const int wn = wid & 1;    // 0..1
    const int row0 = blockIdx.x * TILE_M;

    uint32_t rawb = smem_u32(dynraw);
    uint32_t dynb = (rawb + 127u) & ~127u;

    for (int i = tid; i < ATTD; i += 256) wf_s[i] = W_full[i];
    if (tid < TILE_M) att_acc[tid] = 0.f;
    __syncthreads();

    // ---- x loader mapping: thread -> (row xm, k-half xh of 16 elems) ----
    const int xm = tid >> 1, xh = tid & 1;
    const float4* xg = reinterpret_cast<const float4*>(x) +
                       ((size_t)(row0 + xm) * ENC) / 4 + xh * 4;
    const int xsw = (xm >> 1) & 3;
    // ---- W loader: per hl, tasks i = tid + 256*j -> (row i>>2, chunk i&3) ----

    // ldmatrix lane geometry
    const int a_r = wm * 32 + (lane & 7) + (lane & 8);
    const int a_hi = lane >> 4;
    const int b_r = wn * 128 + (lane & 7) + ((lane >> 1) & 8);
    const int b_hi = (lane >> 3) & 1;

    for (int nb = 0; nb < NB_CHUNKS; nb++) {
        float acc[2][16][4];
#pragma unroll
        for (int mt = 0; mt < 2; mt++)
#pragma unroll
            for (int nt = 0; nt < 16; nt++)
#pragma unroll
                for (int q = 0; q < 4; q++) acc[mt][nt][q] = 0.f;

        // ---- prologue: W stages 0..2, x stage 0 ----
#pragma unroll
        for (int p = 0; p < 3; p++) {
#pragma unroll
            for (int hl = 0; hl < 2; hl++)
#pragma unroll
                for (int j = 0; j < 4; j++) {
                    int i = tid + 256 * j;
                    int row = i >> 2, c = i & 3;
                    uint32_t dst = dynb + WBASE + p * WSTG + hl * 16384 +
                                   row * 64 + (((c ^ ((row >> 1) & 3)) << 4));
                    const unsigned char* src = g_Wt + (size_t)hl * 2097152 +
                        (size_t)(nb * 256 + row) * 4096 + (size_t)(p * KBLK + c * 8) * 2;
                    CP_ASYNC16(dst, src);
                }
            CP_COMMIT();
        }
        {   // x stage 0
            float4 x0[4];
#pragma unroll
            for (int j = 0; j < 4; j++) x0[j] = xg[j];
            const float* e = reinterpret_cast<const float*>(x0);
            uint32_t hw[8], lw[8];
#pragma unroll
            for (int q = 0; q < 8; q++) {
                float v0 = e[2 * q], v1 = e[2 * q + 1];
                float h0 = __bfloat162float(__float2bfloat16_rn(v0));
                float h1 = __bfloat162float(__float2bfloat16_rn(v1));
                hw[q] = pack2(h0, h1);
                lw[q] = pack2(v0 - h0, v1 - h1);
            }
#pragma unroll
            for (int j = 0; j < 2; j++) {
                int swo = xm * 64 + (((xh * 2 + j) ^ xsw) << 4);
                *reinterpret_cast<uint4*>(dynraw + (dynb - rawb) + swo) =
                    make_uint4(hw[4 * j], hw[4 * j + 1], hw[4 * j + 2], hw[4 * j + 3]);
                *reinterpret_cast<uint4*>(dynraw + (dynb - rawb) + 8192 + swo) =
                    make_uint4(lw[4 * j], lw[4 * j + 1], lw[4 * j + 2], lw[4 * j + 3]);
            }
        }

        for (int kblk = 0; kblk < NKB; kblk++) {
            const bool more = (kblk + 1 < NKB);
            float4 xr[4];
            if (more) {
                const float4* p = xg + (kblk + 1) * (KBLK / 4);
#pragma unroll
                for (int j = 0; j < 4; j++) xr[j] = p[j];
            }
            CP_WAIT2();
            __syncthreads();   // stage kblk%4 (W + x) visible; stage (kblk+3)%4 free

            // issue W(kblk+3) (or empty group to keep the count)
            if (kblk + 3 < NKB) {
                const int ws = (kblk + 3) & 3;
#pragma unroll
                for (int hl = 0; hl < 2; hl++)
#pragma unroll
                    for (int j = 0; j < 4; j++) {
                        int i = tid + 256 * j;
                        int row = i >> 2, c = i & 3;
                        uint32_t dst = dynb + WBASE + ws * WSTG + hl * 16384 +
                                       row * 64 + (((c ^ ((row >> 1) & 3)) << 4));
                        const unsigned char* src = g_Wt + (size_t)hl * 2097152 +
                            (size_t)(nb * 256 + row) * 4096 +
                            (size_t)((kblk + 3) * KBLK + c * 8) * 2;
                        CP_ASYNC16(dst, src);
                    }
            }
            CP_COMMIT();

            // ---- MMA on stage kblk%4 ----
            {
                const uint32_t xsb = dynb + (kblk & 3) * XSTG;
                const uint32_t wsb = dynb + WBASE + (kblk & 3) * WSTG;
#pragma unroll
                for (int ks = 0; ks < 2; ks++) {
                    uint32_t ah[2][4], al[2][4];
#pragma unroll
                    for (int mt = 0; mt < 2; mt++) {
                        int row = a_r + mt * 16;
                        uint32_t ad = xsb + row * 64 +
                                      (((ks * 2 + a_hi) ^ ((row >> 1) & 3)) << 4);
                        LDSM_X4(ah[mt], ad);
                        LDSM_X4(al[mt], ad + 8192);
                    }
#pragma unroll
                    for (int ntp = 0; ntp < 8; ntp++) {
                        int row = b_r + ntp * 16;
                        uint32_t bd = wsb + row * 64 +
                                      (((ks * 2 + b_hi) ^ ((row >> 1) & 3)) << 4);
                        uint32_t bh[4], bl[4];
                        LDSM_X4(bh, bd);
                        LDSM_X4(bl, bd + 16384);
#pragma unroll
                        for (int mt = 0; mt < 2; mt++) {
                            MMA_BF16(acc[mt][2 * ntp],     ah[mt], bh + 0);
                            MMA_BF16(acc[mt][2 * ntp + 1], ah[mt], bh + 2);
                            MMA_BF16(acc[mt][2 * ntp],     ah[mt], bl + 0);
                            MMA_BF16(acc[mt][2 * ntp + 1], ah[mt], bl + 2);
                            MMA_BF16(acc[mt][2 * ntp],     al[mt], bh + 0);
                            MMA_BF16(acc[mt][2 * ntp + 1], al[mt], bh + 2);
                        }
                    }
                }
            }

            // ---- convert + STS x(kblk+1) into stage (kblk+1)%4 ----
            if (more) {
                const int xs = (kblk + 1) & 3;
                const float* e = reinterpret_cast<const float*>(xr);
                uint32_t hw[8], lw[8];
#pragma unroll
                for (int q = 0; q < 8; q++) {
                    float v0 = e[2 * q], v1 = e[2 * q + 1];
                    float h0 = __bfloat162float(__float2bfloat16_rn(v0));
                    float h1 = __bfloat162float(__float2bfloat16_rn(v1));
                    hw[q] = pack2(h0, h1);
                    lw[q] = pack2(v0 - h0, v1 - h1);
                }
                unsigned char* xb = dynraw + (dynb - rawb) + xs * XSTG;
#pragma unroll
                for (int j = 0; j < 2; j++) {
                    int swo = xm * 64 + (((xh * 2 + j) ^ xsw) << 4);
                    *reinterpret_cast<uint4*>(xb + swo) =
                        make_uint4(hw[4 * j], hw[4 * j + 1], hw[4 * j + 2], hw[4 * j + 3]);
                    *reinterpret_cast<uint4*>(xb + 8192 + swo) =
                        make_uint4(lw[4 * j], lw[4 * j + 1], lw[4 * j + 2], lw[4 * j + 3]);
                }
            }
        }
        CP_WAIT0();
        __syncthreads();

        // ---- epilogue for this n-chunk ----
#pragma unroll
        for (int mt = 0; mt < 2; mt++)
#pragma unroll
            for (int rh = 0; rh < 2; rh++) {
                int ml = wm * 32 + mt * 16 + (lane >> 2) + rh * 8;
                int gm = row0 + ml;
                int b = gm / LSEQ;
                const float* a2 = g_att2 + (size_t)b * ATTD + nb * 256 + wn * 128;
                const float* wfp = wf_s + nb * 256 + wn * 128;
                float s = 0.f;
#pragma unroll
                for (int nt = 0; nt < 16; nt++) {
#pragma unroll
                    for (int e2 = 0; e2 < 2; e2++) {
                        int nn = nt * 8 + (lane & 3) * 2 + e2;
                        float v = acc[mt][nt][rh * 2 + e2] + __ldg(a2 + nn);
                        s += fmaxf(v, 0.f) * wfp[nn];
                    }
                }
                s += __shfl_xor_sync(0xFFFFFFFF, s, 1);
                s += __shfl_xor_sync(0xFFFFFFFF, s, 2);
                if ((lane & 3) == 0) atomicAdd(&att_acc[ml], s);
            }
        __syncthreads();
    }

    if (tid < TILE_M) g_att[row0 + tid] = att_acc[tid];
}

// ---------------------------------------------------------------------------
__global__ __launch_bounds__(256) void softmax_kernel(float* __restrict__ out_alpha) {
    int b = blockIdx.x, t = threadIdx.x;
    __shared__ float sred[256];
    float v = (t < LSEQ) ? g_att[b * LSEQ + t] : -1e30f;
    sred[t] = v;
    __syncthreads();
    for (int s = 128; s > 0; s >>= 1) {
        if (t < s) sred[t] = fmaxf(sred[t], sred[t + s]);
        __syncthreads();
    }
    float m = sred[0];
    __syncthreads();
    float e = (t < LSEQ) ? expf(v - m) : 0.f;
    sred[t] = e;
    __syncthreads();
    for (int s = 128; s > 0; s >>= 1) {
        if (t < s) sred[t] += sred[t + s];
        __syncthreads();
    }
    float inv = 1.f / sred[0];
    if (t < LSEQ) out_alpha[b * LSEQ + t] = e * inv;
}

__global__ __launch_bounds__(256) void z_kernel(
    const float* __restrict__ x, const float* __restrict__ alpha,
    float* __restrict__ out_z) {
    int b = blockIdx.y;
    int c4 = blockIdx.x * 256 + threadIdx.x;
    __shared__ float sal[LSEQ];
    for (int i = threadIdx.x; i < LSEQ; i += 256) sal[i] = alpha[b * LSEQ + i];
    __syncthreads();
    const float4* xp = reinterpret_cast<const float4*>(x + (size_t)b * LSEQ * ENC) + c4;
    float ax = 0.f, ay = 0.f, az = 0.f, aw = 0.f;
#pragma unroll 4
    for (int l = 0; l < LSEQ; l++) {
        float4 v = xp[(size_t)l * (ENC / 4)];
        float a = sal[l];
        ax += a * v.x; ay += a * v.y; az += a * v.z; aw += a * v.w;
    }
    float g = g_gate[b];
    float4 o;
    o.x = g * ax; o.y = g * ay; o.z = g * az; o.w = g * aw;
    reinterpret_cast<float4*>(out_z)[(size_t)b * (ENC / 4) + c4] = o;
}

// ---------------------------------------------------------------------------
extern "C" void kernel_launch(void* const* d_in, const int* in_sizes, int n_in,
                              void* d_out, int out_size) {
    const float* x      = (const float*)d_in[0];
    const float* h      = (const float*)d_in[1];
    const float* W_enc  = (const float*)d_in[2];
    const float* b_enc  = (const float*)d_in[3];
    const float* W_dec  = (const float*)d_in[4];
    const float* b_dec  = (const float*)d_in[5];
    const float* W_full = (const float*)d_in[6];
    // d_in[7] = b_full: softmax-invariant, unused.
    const float* W_beta = (const float*)d_in[8];
    const float* b_beta = (const float*)d_in[9];

    float* out = (float*)d_out;
    float* out_z = out;
    float* out_alpha = out + (size_t)BATCH * ENC;

    cudaFuncSetAttribute(att_gemm_mma, cudaFuncAttributeMaxDynamicSharedMemorySize, DYN_BYTES);

    prep_w<<<dim3(ENC / 64, ATTD / 64), 256>>>(W_enc);
    att2_kernel<<<BATCH, 256>>>(h, W_dec, b_dec, b_enc, W_beta, b_beta);
    att_gemm_mma<<<NCTA, 256, DYN_BYTES>>>(x, W_full);
    softmax_kernel<<<BATCH, 256>>>(out_alpha);
    z_kernel<<<dim3(ENC / 1024, BATCH), 256>>>(x, out_alpha, out_z);
}